// round 15
// baseline (speedup 1.0000x reference)
#include <cuda_runtime.h>
#include <math.h>

#define B_DIM 8
#define L_DIM 2048
#define TOPK 30
#define NROWS (B_DIM * L_DIM)          // 16384
#define NEDGES (NROWS * TOPK)          // 491520
#define E_ELEMS ((size_t)NEDGES * 128) // 62914560
#define NFEAT 147                      // 144 rbf + 3 sh (pos folded into T)

#define TILE_E 8                       // edges per tile (8,8,8,6)
#define NTILES 4
#define FSTRIDE 148                    // padded feature row per edge (f=147 is zero)
#define LSTRIDE 596                    // per-lane weight stride (149*4 floats, conflict-free)
#define W3_FLOATS (32 * LSTRIDE)       // 19072
#define FT_FLOATS (TILE_E * FSTRIDE)   // 1184 floats per warp
#define EW 8                           // warps per CTA (256 threads, 2 CTAs/SM)
#define SMEM_FLOATS (W3_FLOATS + EW * FT_FLOATS)   // 28544 floats = 111.5 KB

// ---------------- device scratch (no allocations allowed) ----------------
__device__ int   g_Eidx[NEDGES];
__device__ float g_Dnb[NEDGES];
__device__ float g_SH[NROWS * 3];
__device__ float g_T[66 * 128];          // folded positional table: T[d][c]
__device__ float g_Wt3[W3_FLOATS];       // per-lane paired weights
__device__ int   g_chainStride;          // 2 if chain_labels is int64, 1 if 32-bit
__device__ float g_Cx[NROWS], g_Cy[NROWS], g_Cz[NROWS];   // SoA coords

static __device__ __forceinline__ unsigned long long u64min(unsigned long long a, unsigned long long b) {
    return a < b ? a : b;
}

// XLA-bit-exact squared distance + sqrt: no FMA contraction, left-to-right adds.
static __device__ __forceinline__ float xla_dist(float dx, float dy, float dz) {
    float d2 = __fadd_rn(__fadd_rn(__fmul_rn(dx, dx), __fmul_rn(dy, dy)), __fmul_rn(dz, dz));
    return __fsqrt_rn(__fadd_rn(d2, 1e-6f));
}

#define FMA2(d, a, b) asm("fma.rn.f32x2 %0, %1, %2, %0;" : "+l"(d) : "l"(a), "l"(b))
#define UNPACK2(lo, hi, a) asm("mov.b64 {%0, %1}, %2;" : "=r"(lo), "=r"(hi) : "l"(a))
#define CASW(x, y) { unsigned long long _mn = u64min(x, y); y = x ^ y ^ _mn; x = _mn; }

// ---------------- prep: fold positional path + per-lane weights + dtype probe + SoA ----------------
__global__ void prep_kernel(const float* __restrict__ W_edge,
                            const float* __restrict__ W_pos,
                            const float* __restrict__ b_pos,
                            const unsigned int* __restrict__ chains_w,
                            const float* __restrict__ Ca) {
    int tid = blockIdx.x * blockDim.x + threadIdx.x;
    if (tid == 0) {
        int stride = 2;
        for (int t = 1; t < 512; t += 2) {
            if (chains_w[t] != 0u) { stride = 1; break; }
        }
        g_chainStride = stride;
    }
    if (tid < NROWS) {
        g_Cx[tid] = Ca[tid * 3];
        g_Cy[tid] = Ca[tid * 3 + 1];
        g_Cz[tid] = Ca[tid * 3 + 2];
    }
    if (tid < 66 * 128) {
        int d = tid >> 7, c = tid & 127;
        float s = 0.f;
        #pragma unroll
        for (int p = 0; p < 16; p++)
            s += W_edge[c * 163 + p] * (W_pos[p * 66 + d] + b_pos[p]);
        g_T[tid] = s;   // g_T[d*128 + c]
    }
    int t2 = tid - 66 * 128;
    if (t2 >= 0 && t2 < W3_FLOATS) {
        int lane = t2 / LSTRIDE, r = t2 % LSTRIDE;
        int pp = r >> 3, q = r & 7;
        int f = 2 * pp + (q & 1);
        int c = lane * 4 + (q >> 1);
        float v = 0.f;
        if (f < NFEAT) {
            int col = (f < 144) ? (16 + f) : (160 + (f - 144));
            v = W_edge[c * 163 + col];
        }
        g_Wt3[t2] = v;   // Wt3[lane*596 + pp*8 + 2*ch + s] = W(2pp+s, lane*4+ch)
    }
}

// ---------------- spherical harmonics closed form ----------------
__global__ void sh_kernel(const float* __restrict__ Ca) {
    int idx = blockIdx.x * blockDim.x + threadIdx.x;
    if (idx >= NROWS) return;
    float x = Ca[idx * 3], y = Ca[idx * 3 + 1], z = Ca[idx * 3 + 2];
    float r = sqrtf(x * x + y * y + z * z);
    float phi = atan2f(y, x);
    float cp = cosf(phi);
    float s2 = 1.f - cp * cp;
    float cp2 = cp * cp;

    const float INV4PI = 0.07957747154594767f;
    float a00 = INV4PI;
    float f0 = sqrtf(a00 * a00);

    float a10 = 3.f * INV4PI, a11 = 0.5f * a10, a1m = 2.f * a10;
    float acc1 = a10 * a10 * cp2 + (a11 * a11 + 0.25f * a1m * a1m) * cp2 * s2;
    float f1 = sqrtf(acc1);

    float a20 = 5.f * INV4PI, a21 = a20 / 6.f, a2m1 = a20 * 6.f;
    float a22 = a20 / 24.f, a2m2 = a20 * 24.f;
    float p20 = 0.5f * (3.f * cp2 - 1.f);
    float c2 = cosf(2.f * phi);
    float acc2 = a20 * a20 * p20 * p20
               + (9.f * a21 * a21 + 0.25f * a2m1 * a2m1) * cp2 * cp2 * s2
               + (9.f * a22 * a22 + a2m2 * a2m2 * (1.f / 64.f)) * c2 * c2 * s2 * s2;
    float f2 = sqrtf(acc2);

    float q = z / r;
    bool bad = !(q >= -1.f && q <= 1.f);   // catches |q|>1 and NaN (r==0)
    if (bad || !(f0 == f0)) f0 = 0.f;
    if (bad || !(f1 == f1)) f1 = 0.f;
    if (bad || !(f2 == f2)) f2 = 0.f;
    g_SH[idx * 3]     = f0;
    g_SH[idx * 3 + 1] = f1;
    g_SH[idx * 3 + 2] = f2;
}

// ---------------- top-k: sorted heads + tournament + rank merge ----------------
__global__ void __launch_bounds__(256) topk_kernel(const float* __restrict__ mask,
                                                   float* __restrict__ outIdx,
                                                   int writeIdx) {
    const int row = blockIdx.x;
    const int b = row >> 11, i = row & (L_DIM - 1);
    const int tid = threadIdx.x;
    const int warp = tid >> 5, lane = tid & 31;
    const int base = b << 11;
    float cx = g_Cx[base + i], cy = g_Cy[base + i], cz = g_Cz[base + i];
    float mi = mask[row];

    float Dv[8], mm[8];
    float lmax = 0.f;
    #pragma unroll
    for (int t = 0; t < 8; t++) {
        int j = tid + (t << 8);
        float dx = __fadd_rn(cx, -g_Cx[base + j]);
        float dy = __fadd_rn(cy, -g_Cy[base + j]);
        float dz = __fadd_rn(cz, -g_Cz[base + j]);
        float sd = xla_dist(dx, dy, dz);
        float mij = __fmul_rn(mi, mask[base + j]);
        float D = __fmul_rn(mij, sd);
        Dv[t] = D; mm[t] = mij;
        lmax = fmaxf(lmax, D);
    }

    __shared__ float sred[8];
    #pragma unroll
    for (int o = 16; o; o >>= 1) lmax = fmaxf(lmax, __shfl_xor_sync(0xffffffffu, lmax, o));
    if (lane == 0) sred[warp] = lmax;
    __syncthreads();
    float Dmax = sred[0];
    #pragma unroll
    for (int w = 1; w < 8; w++) Dmax = fmaxf(Dmax, sred[w]);

    // keys: (value bits << 32) | j ; exact jax.top_k ordering
    unsigned long long k0, k1, k2, k3, k4, k5, k6, k7;
    {
        unsigned long long kk[8];
        #pragma unroll
        for (int t = 0; t < 8; t++) {
            float kf = __fadd_rn(Dv[t], __fmul_rn(__fadd_rn(1.f, -mm[t]), Dmax));
            kk[t] = ((unsigned long long)__float_as_uint(kf) << 32) | (unsigned)(tid + (t << 8));
        }
        k0 = kk[0]; k1 = kk[1]; k2 = kk[2]; k3 = kk[3];
        k4 = kk[4]; k5 = kk[5]; k6 = kk[6]; k7 = kk[7];
    }

    // Batcher odd-even mergesort, 19 comparators -> ascending
    CASW(k0, k1); CASW(k2, k3); CASW(k4, k5); CASW(k6, k7);
    CASW(k0, k2); CASW(k1, k3); CASW(k4, k6); CASW(k5, k7);
    CASW(k1, k2); CASW(k5, k6);
    CASW(k0, k4); CASW(k1, k5); CASW(k2, k6); CASW(k3, k7);
    CASW(k2, k4); CASW(k3, k5);
    CASW(k1, k2); CASW(k3, k4); CASW(k5, k6);

    __shared__ unsigned long long sortedK[8][32][8];
    __shared__ unsigned long long warpTop[8][32];
    unsigned long long* myS = sortedK[warp][lane];
    myS[0] = k0; myS[1] = k1; myS[2] = k2; myS[3] = k3;
    myS[4] = k4; myS[5] = k5; myS[6] = k6; myS[7] = k7;

    const unsigned long long INF64 = 0xFFFFFFFFFFFFFFFFull;
    unsigned long long h = k0;
    int pos = 0;

    // Phase A: per-warp top-30 via head tournament (32-bit value min + ballot)
    for (int r = 0; r < TOPK; r++) {
        unsigned v = (unsigned)(h >> 32);
        unsigned m = v;
        #pragma unroll
        for (int o = 16; o; o >>= 1) m = min(m, __shfl_xor_sync(0xffffffffu, m, o));
        unsigned eq = __ballot_sync(0xffffffffu, v == m);
        int wl;
        if ((eq & (eq - 1)) == 0u) {
            wl = __ffs(eq) - 1;
        } else {
            // value tie: lowest index wins (exact jax semantics)
            unsigned ic = (v == m) ? (unsigned)h : 0xFFFFFFFFu;
            unsigned mi2 = ic;
            #pragma unroll
            for (int o = 16; o; o >>= 1) mi2 = min(mi2, __shfl_xor_sync(0xffffffffu, mi2, o));
            wl = __ffs(__ballot_sync(0xffffffffu, ic == mi2)) - 1;
        }
        unsigned long long hw = __shfl_sync(0xffffffffu, h, wl);
        if (lane == 0) warpTop[warp][r] = hw;
        if (lane == wl) {
            pos++;
            h = (pos < 8) ? myS[pos] : INF64;
        }
    }
    if (lane == 0) { warpTop[warp][30] = INF64; warpTop[warp][31] = INF64; }
    __syncthreads();

    // Phase B: one-shot rank merge of 8 sorted lists of 30
    if (tid < 8 * TOPK) {
        int lw = tid / TOPK, lp = tid - lw * TOPK;
        unsigned long long c = warpTop[lw][lp];
        int rank = lp;
        #pragma unroll
        for (int w = 0; w < 8; w++) {
            if (w == lw) continue;
            const unsigned long long* L = warpTop[w];
            int p = 0;
            if (L[p + 15] < c) p += 16;
            if (L[p + 7]  < c) p += 8;
            if (L[p + 3]  < c) p += 4;
            if (L[p + 1]  < c) p += 2;
            if (L[p]      < c) p += 1;
            rank += p;
        }
        if (rank < TOPK) {
            int j = (int)(c & 0xFFFFFFFFull);
            g_Eidx[row * TOPK + rank] = j;
            g_Dnb[row * TOPK + rank] = __uint_as_float((unsigned)(c >> 32));
            if (writeIdx) outIdx[row * TOPK + rank] = (float)j;
        }
    }
}

// ---------------- edge kernel: K-packed f32x2 GEMV + LayerNorm, 2 CTAs/SM ----------------
__global__ void __launch_bounds__(256, 2)
edge_kernel(const float* __restrict__ Ca,
            const unsigned int* __restrict__ chains_w,
            const float* __restrict__ gamma,
            const float* __restrict__ beta,
            float* __restrict__ outE) {
    extern __shared__ float smem[];
    float* Wt3 = smem;
    const int warp = threadIdx.x >> 5, lane = threadIdx.x & 31;

    for (int idx = threadIdx.x; idx < W3_FLOATS; idx += 256) Wt3[idx] = g_Wt3[idx];
    __syncthreads();

    float* featsT = smem + W3_FLOATS + warp * FT_FLOATS;   // [e][f], FSTRIDE=148

    const int row = blockIdx.x * EW + warp;
    const int b = row >> 11, i = row & (L_DIM - 1);
    const float* Cb = Ca + (size_t)(b << 11) * 3;
    const int cstr = g_chainStride;

    float3 Ci  = make_float3(Cb[i * 3], Cb[i * 3 + 1], Cb[i * 3 + 2]);
    float3 Ci0 = (i > 0) ? make_float3(Cb[(i - 1) * 3], Cb[(i - 1) * 3 + 1], Cb[(i - 1) * 3 + 2])
                         : make_float3(0.f, 0.f, 0.f);
    float3 Ci2 = (i < L_DIM - 1) ? make_float3(Cb[(i + 1) * 3], Cb[(i + 1) * 3 + 1], Cb[(i + 1) * 3 + 2])
                                 : make_float3(0.f, 0.f, 0.f);
    unsigned int chi = chains_w[(size_t)row * cstr];

    // block (1..8) A/B source codes: 0=Ca_prev 1=Ca 2=Ca_next
    int li = (lane >= 1) ? ((lane - 1) & 7) : 0;
    int ac = (int)((0x22110020u >> (li << 2)) & 3u);
    int bc = (int)((0x10202120u >> (li << 2)) & 3u);
    float3 Apt = (ac == 0) ? Ci0 : ((ac == 1) ? Ci : Ci2);

    const int c0 = lane << 2;
    float4 g4  = *(const float4*)&gamma[c0];
    float4 be4 = *(const float4*)&beta[c0];
    const float* wlane = Wt3 + lane * LSTRIDE;

    for (int tile = 0; tile < NTILES; tile++) {
        const int k0 = tile * TILE_E;
        const int ec = (tile < 3) ? TILE_E : 6;

        int jj = 0; float D0 = 0.f; int didx = 65;
        if (lane < ec) {
            jj = g_Eidx[row * TOPK + k0 + lane];
            D0 = g_Dnb[row * TOPK + k0 + lane];
            unsigned int cj = chains_w[(size_t)((b << 11) + jj) * cstr];
            int off = i - jj + 32;                  // residue_idx is arange(L)
            off = off < 0 ? 0 : (off > 64 ? 64 : off);
            didx = (chi == cj) ? off : 65;
        }
        __syncwarp();

        // ---- feature generation into featsT[e][f] (coalesced STS) ----
        for (int e = 0; e < ec; e++) {
            int   je  = __shfl_sync(0xffffffffu, jj, e);
            float D0e = __shfl_sync(0xffffffffu, D0, e);
            float dv = D0e;                       // lane 0 = block 0 (D_neighbors)
            int jb = je + bc - 1;
            bool valid = (bc == 1) || (jb >= 0 && jb <= L_DIM - 1);
            float bx = 0.f, by = 0.f, bz = 0.f;
            if (lane >= 1 && lane <= 8 && valid) {
                bx = Cb[jb * 3]; by = Cb[jb * 3 + 1]; bz = Cb[jb * 3 + 2];
            }
            if (lane >= 1 && lane <= 8) {
                float dx = Apt.x - bx, dy = Apt.y - by, dz = Apt.z - bz;
                dv = sqrtf(dx * dx + dy * dy + dz * dz + 1e-6f);
            }
            float* fre = featsT + e * FSTRIDE;
            #pragma unroll
            for (int t = 0; t < 4; t++) {
                int f = lane + (t << 5);          // 0..127, all RBF
                int blk = f >> 4;
                float dd = __shfl_sync(0xffffffffu, dv, blk);
                float m = (float)(f & 15);
                float u = (dd - (2.f + m * (4.f / 3.f))) * 0.8f;
                fre[f] = __expf(-u * u);
            }
            {   // t = 4: f = 128 + lane
                int f = 128 + lane;
                float dd = __shfl_sync(0xffffffffu, dv, 8);
                if (f < 144) {
                    float m = (float)(f & 15);
                    float u = (dd - (2.f + m * (4.f / 3.f))) * 0.8f;
                    fre[f] = __expf(-u * u);
                } else if (f < 147) {
                    fre[f] = g_SH[((b << 11) + je) * 3 + (f - 144)];
                } else if (f == 147) {
                    fre[f] = 0.f;
                }
            }
        }
        __syncwarp();

        // ---- GEMV: K-packed f32x2 with register double-buffered weights ----
        unsigned long long acc[TILE_E][4];
        #pragma unroll
        for (int e = 0; e < TILE_E; e++)
            #pragma unroll
            for (int j = 0; j < 4; j++) acc[e][j] = 0ull;

        ulonglong2 wa = *(const ulonglong2*)wlane;
        ulonglong2 wb = *(const ulonglong2*)(wlane + 4);
        ulonglong2 wc = *(const ulonglong2*)(wlane + 8);
        ulonglong2 wd = *(const ulonglong2*)(wlane + 12);

        #pragma unroll 1
        for (int p2 = 0; p2 < 37; p2++) {   // 2 fpairs (4 features) per iteration
            // prefetch next iteration's weights (last iter reads scratch past
            // the table into the feats region -- in-bounds smem, values unused)
            const float* wrn = wlane + ((p2 + 1) << 4);
            ulonglong2 na = *(const ulonglong2*)wrn;
            ulonglong2 nb = *(const ulonglong2*)(wrn + 4);
            ulonglong2 nc = *(const ulonglong2*)(wrn + 8);
            ulonglong2 nd = *(const ulonglong2*)(wrn + 12);
            #pragma unroll
            for (int e = 0; e < TILE_E; e++) {
                ulonglong2 fe = *(const ulonglong2*)(featsT + e * FSTRIDE + (p2 << 2));
                FMA2(acc[e][0], fe.x, wa.x);
                FMA2(acc[e][1], fe.x, wa.y);
                FMA2(acc[e][2], fe.x, wb.x);
                FMA2(acc[e][3], fe.x, wb.y);
                FMA2(acc[e][0], fe.y, wc.x);
                FMA2(acc[e][1], fe.y, wc.y);
                FMA2(acc[e][2], fe.y, wd.x);
                FMA2(acc[e][3], fe.y, wd.y);
            }
            wa = na; wb = nb; wc = nc; wd = nd;
        }

        // ---- epilogue: resolve halves, + positional table, LayerNorm, store ----
        for (int e = 0; e < ec; e++) {
            int de = __shfl_sync(0xffffffffu, didx, e);
            float4 t4 = *(const float4*)&g_T[(de << 7) + c0];
            float x[4];
            #pragma unroll
            for (int j = 0; j < 4; j++) {
                unsigned int lo, hi;
                UNPACK2(lo, hi, acc[e][j]);
                x[j] = __uint_as_float(lo) + __uint_as_float(hi);
            }
            x[0] += t4.x; x[1] += t4.y; x[2] += t4.z; x[3] += t4.w;

            float s = x[0] + x[1] + x[2] + x[3];
            #pragma unroll
            for (int o = 16; o; o >>= 1) s += __shfl_xor_sync(0xffffffffu, s, o);
            float mu = s * (1.f / 128.f);
            float ss = 0.f;
            #pragma unroll
            for (int j = 0; j < 4; j++) { x[j] -= mu; ss += x[j] * x[j]; }
            #pragma unroll
            for (int o = 16; o; o >>= 1) ss += __shfl_xor_sync(0xffffffffu, ss, o);
            float rstd = rsqrtf(ss * (1.f / 128.f) + 1e-5f);
            float4 o4;
            o4.x = x[0] * rstd * g4.x + be4.x;
            o4.y = x[1] * rstd * g4.y + be4.y;
            o4.z = x[2] * rstd * g4.z + be4.z;
            o4.w = x[3] * rstd * g4.w + be4.w;
            *(float4*)&outE[(((size_t)row * TOPK) + k0 + e) * 128 + c0] = o4;
        }
        __syncwarp();
    }
}

// ---------------- launch ----------------
extern "C" void kernel_launch(void* const* d_in, const int* in_sizes, int n_in,
                              void* d_out, int out_size) {
    const float* Ca     = (const float*)d_in[0];
    const float* mask   = (const float*)d_in[1];
    const unsigned int* chains_w = (const unsigned int*)d_in[3];
    const float* W_pos  = (const float*)d_in[4];
    const float* b_pos  = (const float*)d_in[5];
    const float* W_edge = (const float*)d_in[6];
    const float* gamma  = (const float*)d_in[7];
    const float* beta   = (const float*)d_in[8];
    float* out = (float*)d_out;

    int writeIdx = ((size_t)out_size >= E_ELEMS + (size_t)NEDGES) ? 1 : 0;

    prep_kernel<<<(66 * 128 + W3_FLOATS + 255) / 256, 256>>>(W_edge, W_pos, b_pos, chains_w, Ca);
    sh_kernel<<<(NROWS + 255) / 256, 256>>>(Ca);
    topk_kernel<<<NROWS, 256>>>(mask, out + E_ELEMS, writeIdx);

    cudaFuncSetAttribute(edge_kernel, cudaFuncAttributeMaxDynamicSharedMemorySize,
                         SMEM_FLOATS * sizeof(float));
    edge_kernel<<<NROWS / EW, 256, SMEM_FLOATS * sizeof(float)>>>(
        Ca, chains_w, gamma, beta, out);
}

// round 16
// speedup vs baseline: 1.0297x; 1.0297x over previous
#include <cuda_runtime.h>
#include <math.h>

#define B_DIM 8
#define L_DIM 2048
#define TOPK 30
#define NROWS (B_DIM * L_DIM)          // 16384
#define NEDGES (NROWS * TOPK)          // 491520
#define E_ELEMS ((size_t)NEDGES * 128) // 62914560
#define NFEAT 147                      // 144 rbf + 3 sh (pos folded into T)

#define TILE_E 6                       // edges per tile (5 tiles, no tail)
#define NTILES 5
#define FSTRIDE 148                    // padded feature row per edge (f=147 is zero)
#define LSTRIDE 596                    // per-lane weight stride (149*4 floats, conflict-free)
#define W3_FLOATS (32 * LSTRIDE)       // 19072
#define FT_FLOATS (TILE_E * FSTRIDE)   // 888 floats per warp
#define EW 8                           // warps per CTA (256 threads, 2 CTAs/SM)
#define SMEM_FLOATS (W3_FLOATS + EW * FT_FLOATS)   // 26176 floats = 102.25 KB

// ---------------- device scratch (no allocations allowed) ----------------
__device__ int   g_Eidx[NEDGES];
__device__ float g_Dnb[NEDGES];
__device__ float g_SH[NROWS * 3];
__device__ float g_T[66 * 128];          // folded positional table: T[d][c]
__device__ float g_Wt3[W3_FLOATS];       // per-lane paired weights
__device__ int   g_chainStride;          // 2 if chain_labels is int64, 1 if 32-bit
__device__ float g_Cx[NROWS], g_Cy[NROWS], g_Cz[NROWS];   // SoA coords

static __device__ __forceinline__ unsigned long long u64min(unsigned long long a, unsigned long long b) {
    return a < b ? a : b;
}

// XLA-bit-exact squared distance + sqrt: no FMA contraction, left-to-right adds.
static __device__ __forceinline__ float xla_dist(float dx, float dy, float dz) {
    float d2 = __fadd_rn(__fadd_rn(__fmul_rn(dx, dx), __fmul_rn(dy, dy)), __fmul_rn(dz, dz));
    return __fsqrt_rn(__fadd_rn(d2, 1e-6f));
}

#define FMA2(d, a, b) asm("fma.rn.f32x2 %0, %1, %2, %0;" : "+l"(d) : "l"(a), "l"(b))
#define UNPACK2(lo, hi, a) asm("mov.b64 {%0, %1}, %2;" : "=r"(lo), "=r"(hi) : "l"(a))
#define CASW(x, y) { unsigned long long _mn = u64min(x, y); y = x ^ y ^ _mn; x = _mn; }

// ---------------- prep: fold pos path + per-lane weights + probe + SoA + SH ----------------
__global__ void prep_kernel(const float* __restrict__ W_edge,
                            const float* __restrict__ W_pos,
                            const float* __restrict__ b_pos,
                            const unsigned int* __restrict__ chains_w,
                            const float* __restrict__ Ca) {
    int tid = blockIdx.x * blockDim.x + threadIdx.x;
    if (tid == 0) {
        int stride = 2;
        for (int t = 1; t < 512; t += 2) {
            if (chains_w[t] != 0u) { stride = 1; break; }
        }
        g_chainStride = stride;
    }
    if (tid < NROWS) {
        float x = Ca[tid * 3], y = Ca[tid * 3 + 1], z = Ca[tid * 3 + 2];
        g_Cx[tid] = x; g_Cy[tid] = y; g_Cz[tid] = z;

        // spherical harmonics closed form
        float r = sqrtf(x * x + y * y + z * z);
        float phi = atan2f(y, x);
        float cp = cosf(phi);
        float s2 = 1.f - cp * cp;
        float cp2 = cp * cp;

        const float INV4PI = 0.07957747154594767f;
        float a00 = INV4PI;
        float f0 = sqrtf(a00 * a00);

        float a10 = 3.f * INV4PI, a11 = 0.5f * a10, a1m = 2.f * a10;
        float acc1 = a10 * a10 * cp2 + (a11 * a11 + 0.25f * a1m * a1m) * cp2 * s2;
        float f1 = sqrtf(acc1);

        float a20 = 5.f * INV4PI, a21 = a20 / 6.f, a2m1 = a20 * 6.f;
        float a22 = a20 / 24.f, a2m2 = a20 * 24.f;
        float p20 = 0.5f * (3.f * cp2 - 1.f);
        float c2 = cosf(2.f * phi);
        float acc2 = a20 * a20 * p20 * p20
                   + (9.f * a21 * a21 + 0.25f * a2m1 * a2m1) * cp2 * cp2 * s2
                   + (9.f * a22 * a22 + a2m2 * a2m2 * (1.f / 64.f)) * c2 * c2 * s2 * s2;
        float f2 = sqrtf(acc2);

        float q = z / r;
        bool bad = !(q >= -1.f && q <= 1.f);   // catches |q|>1 and NaN (r==0)
        if (bad || !(f0 == f0)) f0 = 0.f;
        if (bad || !(f1 == f1)) f1 = 0.f;
        if (bad || !(f2 == f2)) f2 = 0.f;
        g_SH[tid * 3]     = f0;
        g_SH[tid * 3 + 1] = f1;
        g_SH[tid * 3 + 2] = f2;
    }
    if (tid < 66 * 128) {
        int d = tid >> 7, c = tid & 127;
        float s = 0.f;
        #pragma unroll
        for (int p = 0; p < 16; p++)
            s += W_edge[c * 163 + p] * (W_pos[p * 66 + d] + b_pos[p]);
        g_T[tid] = s;   // g_T[d*128 + c]
    }
    int t2 = tid - 66 * 128;
    if (t2 >= 0 && t2 < W3_FLOATS) {
        int lane = t2 / LSTRIDE, r = t2 % LSTRIDE;
        int pp = r >> 3, q = r & 7;
        int f = 2 * pp + (q & 1);
        int c = lane * 4 + (q >> 1);
        float v = 0.f;
        if (f < NFEAT) {
            int col = (f < 144) ? (16 + f) : (160 + (f - 144));
            v = W_edge[c * 163 + col];
        }
        g_Wt3[t2] = v;   // Wt3[lane*596 + pp*8 + 2*ch + s] = W(2pp+s, lane*4+ch)
    }
}

// ---------------- top-k: sorted heads + tournament + rank merge ----------------
__global__ void __launch_bounds__(256) topk_kernel(const float* __restrict__ mask,
                                                   float* __restrict__ outIdx,
                                                   int writeIdx) {
    const int row = blockIdx.x;
    const int b = row >> 11, i = row & (L_DIM - 1);
    const int tid = threadIdx.x;
    const int warp = tid >> 5, lane = tid & 31;
    const int base = b << 11;
    float cx = g_Cx[base + i], cy = g_Cy[base + i], cz = g_Cz[base + i];
    float mi = mask[row];

    float Dv[8], mm[8];
    float lmax = 0.f;
    #pragma unroll
    for (int t = 0; t < 8; t++) {
        int j = tid + (t << 8);
        float dx = __fadd_rn(cx, -g_Cx[base + j]);
        float dy = __fadd_rn(cy, -g_Cy[base + j]);
        float dz = __fadd_rn(cz, -g_Cz[base + j]);
        float sd = xla_dist(dx, dy, dz);
        float mij = __fmul_rn(mi, mask[base + j]);
        float D = __fmul_rn(mij, sd);
        Dv[t] = D; mm[t] = mij;
        lmax = fmaxf(lmax, D);
    }

    __shared__ float sred[8];
    #pragma unroll
    for (int o = 16; o; o >>= 1) lmax = fmaxf(lmax, __shfl_xor_sync(0xffffffffu, lmax, o));
    if (lane == 0) sred[warp] = lmax;
    __syncthreads();
    float Dmax = sred[0];
    #pragma unroll
    for (int w = 1; w < 8; w++) Dmax = fmaxf(Dmax, sred[w]);

    // keys: (value bits << 32) | j ; exact jax.top_k ordering
    unsigned long long k0, k1, k2, k3, k4, k5, k6, k7;
    {
        unsigned long long kk[8];
        #pragma unroll
        for (int t = 0; t < 8; t++) {
            float kf = __fadd_rn(Dv[t], __fmul_rn(__fadd_rn(1.f, -mm[t]), Dmax));
            kk[t] = ((unsigned long long)__float_as_uint(kf) << 32) | (unsigned)(tid + (t << 8));
        }
        k0 = kk[0]; k1 = kk[1]; k2 = kk[2]; k3 = kk[3];
        k4 = kk[4]; k5 = kk[5]; k6 = kk[6]; k7 = kk[7];
    }

    // Batcher odd-even mergesort, 19 comparators -> ascending
    CASW(k0, k1); CASW(k2, k3); CASW(k4, k5); CASW(k6, k7);
    CASW(k0, k2); CASW(k1, k3); CASW(k4, k6); CASW(k5, k7);
    CASW(k1, k2); CASW(k5, k6);
    CASW(k0, k4); CASW(k1, k5); CASW(k2, k6); CASW(k3, k7);
    CASW(k2, k4); CASW(k3, k5);
    CASW(k1, k2); CASW(k3, k4); CASW(k5, k6);

    __shared__ unsigned long long sortedK[8][32][8];
    __shared__ unsigned long long warpTop[8][32];
    unsigned long long* myS = sortedK[warp][lane];
    myS[0] = k0; myS[1] = k1; myS[2] = k2; myS[3] = k3;
    myS[4] = k4; myS[5] = k5; myS[6] = k6; myS[7] = k7;

    const unsigned long long INF64 = 0xFFFFFFFFFFFFFFFFull;
    unsigned long long h = k0;
    int pos = 0;

    // Phase A: per-warp top-30 via head tournament (32-bit value min + ballot)
    for (int r = 0; r < TOPK; r++) {
        unsigned v = (unsigned)(h >> 32);
        unsigned m = v;
        #pragma unroll
        for (int o = 16; o; o >>= 1) m = min(m, __shfl_xor_sync(0xffffffffu, m, o));
        unsigned eq = __ballot_sync(0xffffffffu, v == m);
        int wl;
        if ((eq & (eq - 1)) == 0u) {
            wl = __ffs(eq) - 1;
        } else {
            // value tie: lowest index wins (exact jax semantics)
            unsigned ic = (v == m) ? (unsigned)h : 0xFFFFFFFFu;
            unsigned mi2 = ic;
            #pragma unroll
            for (int o = 16; o; o >>= 1) mi2 = min(mi2, __shfl_xor_sync(0xffffffffu, mi2, o));
            wl = __ffs(__ballot_sync(0xffffffffu, ic == mi2)) - 1;
        }
        unsigned long long hw = __shfl_sync(0xffffffffu, h, wl);
        if (lane == 0) warpTop[warp][r] = hw;
        if (lane == wl) {
            pos++;
            h = (pos < 8) ? myS[pos] : INF64;
        }
    }
    if (lane == 0) { warpTop[warp][30] = INF64; warpTop[warp][31] = INF64; }
    __syncthreads();

    // Phase B: one-shot rank merge of 8 sorted lists of 30
    if (tid < 8 * TOPK) {
        int lw = tid / TOPK, lp = tid - lw * TOPK;
        unsigned long long c = warpTop[lw][lp];
        int rank = lp;
        #pragma unroll
        for (int w = 0; w < 8; w++) {
            if (w == lw) continue;
            const unsigned long long* L = warpTop[w];
            int p = 0;
            if (L[p + 15] < c) p += 16;
            if (L[p + 7]  < c) p += 8;
            if (L[p + 3]  < c) p += 4;
            if (L[p + 1]  < c) p += 2;
            if (L[p]      < c) p += 1;
            rank += p;
        }
        if (rank < TOPK) {
            int j = (int)(c & 0xFFFFFFFFull);
            g_Eidx[row * TOPK + rank] = j;
            g_Dnb[row * TOPK + rank] = __uint_as_float((unsigned)(c >> 32));
            if (writeIdx) outIdx[row * TOPK + rank] = (float)j;
        }
    }
}

// ---------------- edge kernel: K-packed f32x2 GEMV + LayerNorm, 2 CTAs/SM ----------------
__global__ void __launch_bounds__(256, 2)
edge_kernel(const float* __restrict__ Ca,
            const unsigned int* __restrict__ chains_w,
            const float* __restrict__ gamma,
            const float* __restrict__ beta,
            float* __restrict__ outE) {
    extern __shared__ float smem[];
    float* Wt3 = smem;
    const int warp = threadIdx.x >> 5, lane = threadIdx.x & 31;

    for (int idx = threadIdx.x; idx < W3_FLOATS; idx += 256) Wt3[idx] = g_Wt3[idx];
    __syncthreads();

    float* featsT = smem + W3_FLOATS + warp * FT_FLOATS;   // [e][f], FSTRIDE=148

    const int row = blockIdx.x * EW + warp;
    const int b = row >> 11, i = row & (L_DIM - 1);
    const float* Cb = Ca + (size_t)(b << 11) * 3;
    const int cstr = g_chainStride;

    float3 Ci  = make_float3(Cb[i * 3], Cb[i * 3 + 1], Cb[i * 3 + 2]);
    float3 Ci0 = (i > 0) ? make_float3(Cb[(i - 1) * 3], Cb[(i - 1) * 3 + 1], Cb[(i - 1) * 3 + 2])
                         : make_float3(0.f, 0.f, 0.f);
    float3 Ci2 = (i < L_DIM - 1) ? make_float3(Cb[(i + 1) * 3], Cb[(i + 1) * 3 + 1], Cb[(i + 1) * 3 + 2])
                                 : make_float3(0.f, 0.f, 0.f);
    unsigned int chi = chains_w[(size_t)row * cstr];

    // block (1..8) A/B source codes: 0=Ca_prev 1=Ca 2=Ca_next
    int li = (lane >= 1) ? ((lane - 1) & 7) : 0;
    int ac = (int)((0x22110020u >> (li << 2)) & 3u);
    int bc = (int)((0x10202120u >> (li << 2)) & 3u);
    float3 Apt = (ac == 0) ? Ci0 : ((ac == 1) ? Ci : Ci2);

    const int c0 = lane << 2;
    float4 g4  = *(const float4*)&gamma[c0];
    float4 be4 = *(const float4*)&beta[c0];
    const float* wlane = Wt3 + lane * LSTRIDE;

    for (int tile = 0; tile < NTILES; tile++) {
        const int k0 = tile * TILE_E;

        int jj = 0; float D0 = 0.f; int didx = 65;
        if (lane < TILE_E) {
            jj = g_Eidx[row * TOPK + k0 + lane];
            D0 = g_Dnb[row * TOPK + k0 + lane];
            unsigned int cj = chains_w[(size_t)((b << 11) + jj) * cstr];
            int off = i - jj + 32;                  // residue_idx is arange(L)
            off = off < 0 ? 0 : (off > 64 ? 64 : off);
            didx = (chi == cj) ? off : 65;
        }
        __syncwarp();

        // ---- feature generation into featsT[e][f] (coalesced STS) ----
        #pragma unroll
        for (int e = 0; e < TILE_E; e++) {
            int   je  = __shfl_sync(0xffffffffu, jj, e);
            float D0e = __shfl_sync(0xffffffffu, D0, e);
            float dv = D0e;                       // lane 0 = block 0 (D_neighbors)
            int jb = je + bc - 1;
            bool valid = (bc == 1) || (jb >= 0 && jb <= L_DIM - 1);
            float bx = 0.f, by = 0.f, bz = 0.f;
            if (lane >= 1 && lane <= 8 && valid) {
                bx = Cb[jb * 3]; by = Cb[jb * 3 + 1]; bz = Cb[jb * 3 + 2];
            }
            if (lane >= 1 && lane <= 8) {
                float dx = Apt.x - bx, dy = Apt.y - by, dz = Apt.z - bz;
                dv = sqrtf(dx * dx + dy * dy + dz * dz + 1e-6f);
            }
            float* fre = featsT + e * FSTRIDE;
            #pragma unroll
            for (int t = 0; t < 4; t++) {
                int f = lane + (t << 5);          // 0..127, all RBF
                int blk = f >> 4;
                float dd = __shfl_sync(0xffffffffu, dv, blk);
                float m = (float)(f & 15);
                float u = (dd - (2.f + m * (4.f / 3.f))) * 0.8f;
                fre[f] = __expf(-u * u);
            }
            {   // t = 4: f = 128 + lane
                int f = 128 + lane;
                float dd = __shfl_sync(0xffffffffu, dv, 8);
                if (f < 144) {
                    float m = (float)(f & 15);
                    float u = (dd - (2.f + m * (4.f / 3.f))) * 0.8f;
                    fre[f] = __expf(-u * u);
                } else if (f < 147) {
                    fre[f] = g_SH[((b << 11) + je) * 3 + (f - 144)];
                } else if (f == 147) {
                    fre[f] = 0.f;
                }
            }
        }
        __syncwarp();

        // ---- GEMV: K-packed f32x2, half-prefetched weights ----
        unsigned long long acc[TILE_E][4];
        #pragma unroll
        for (int e = 0; e < TILE_E; e++)
            #pragma unroll
            for (int j = 0; j < 4; j++) acc[e][j] = 0ull;

        ulonglong2 wa = *(const ulonglong2*)wlane;
        ulonglong2 wb = *(const ulonglong2*)(wlane + 4);

        #pragma unroll 1
        for (int p2 = 0; p2 < 37; p2++) {   // 2 fpairs (4 features) per iteration
            const float* wr = wlane + (p2 << 4);
            // prefetch next iteration's first half (last iter reads past the
            // lane's table into the next lane's region -- in-bounds smem, unused)
            const float* wrn = wlane + ((p2 + 1) << 4);
            ulonglong2 na = *(const ulonglong2*)wrn;
            ulonglong2 nb = *(const ulonglong2*)(wrn + 4);
            ulonglong2 wc = *(const ulonglong2*)(wr + 8);
            ulonglong2 wd = *(const ulonglong2*)(wr + 12);
            #pragma unroll
            for (int e = 0; e < TILE_E; e++) {
                ulonglong2 fe = *(const ulonglong2*)(featsT + e * FSTRIDE + (p2 << 2));
                FMA2(acc[e][0], fe.x, wa.x);
                FMA2(acc[e][1], fe.x, wa.y);
                FMA2(acc[e][2], fe.x, wb.x);
                FMA2(acc[e][3], fe.x, wb.y);
                FMA2(acc[e][0], fe.y, wc.x);
                FMA2(acc[e][1], fe.y, wc.y);
                FMA2(acc[e][2], fe.y, wd.x);
                FMA2(acc[e][3], fe.y, wd.y);
            }
            wa = na; wb = nb;
        }

        // ---- epilogue: resolve halves, + positional table, LayerNorm, store ----
        #pragma unroll
        for (int e = 0; e < TILE_E; e++) {
            int de = __shfl_sync(0xffffffffu, didx, e);
            float4 t4 = *(const float4*)&g_T[(de << 7) + c0];
            float x[4];
            #pragma unroll
            for (int j = 0; j < 4; j++) {
                unsigned int lo, hi;
                UNPACK2(lo, hi, acc[e][j]);
                x[j] = __uint_as_float(lo) + __uint_as_float(hi);
            }
            x[0] += t4.x; x[1] += t4.y; x[2] += t4.z; x[3] += t4.w;

            float s = x[0] + x[1] + x[2] + x[3];
            #pragma unroll
            for (int o = 16; o; o >>= 1) s += __shfl_xor_sync(0xffffffffu, s, o);
            float mu = s * (1.f / 128.f);
            float ss = 0.f;
            #pragma unroll
            for (int j = 0; j < 4; j++) { x[j] -= mu; ss += x[j] * x[j]; }
            #pragma unroll
            for (int o = 16; o; o >>= 1) ss += __shfl_xor_sync(0xffffffffu, ss, o);
            float rstd = rsqrtf(ss * (1.f / 128.f) + 1e-5f);
            float4 o4;
            o4.x = x[0] * rstd * g4.x + be4.x;
            o4.y = x[1] * rstd * g4.y + be4.y;
            o4.z = x[2] * rstd * g4.z + be4.z;
            o4.w = x[3] * rstd * g4.w + be4.w;
            *(float4*)&outE[(((size_t)row * TOPK) + k0 + e) * 128 + c0] = o4;
        }
        __syncwarp();
    }
}

// ---------------- launch ----------------
extern "C" void kernel_launch(void* const* d_in, const int* in_sizes, int n_in,
                              void* d_out, int out_size) {
    const float* Ca     = (const float*)d_in[0];
    const float* mask   = (const float*)d_in[1];
    const unsigned int* chains_w = (const unsigned int*)d_in[3];
    const float* W_pos  = (const float*)d_in[4];
    const float* b_pos  = (const float*)d_in[5];
    const float* W_edge = (const float*)d_in[6];
    const float* gamma  = (const float*)d_in[7];
    const float* beta   = (const float*)d_in[8];
    float* out = (float*)d_out;

    int writeIdx = ((size_t)out_size >= E_ELEMS + (size_t)NEDGES) ? 1 : 0;

    prep_kernel<<<(66 * 128 + W3_FLOATS + 255) / 256, 256>>>(W_edge, W_pos, b_pos, chains_w, Ca);
    topk_kernel<<<NROWS, 256>>>(mask, out + E_ELEMS, writeIdx);

    cudaFuncSetAttribute(edge_kernel, cudaFuncAttributeMaxDynamicSharedMemorySize,
                         SMEM_FLOATS * sizeof(float));
    edge_kernel<<<NROWS / EW, 256, SMEM_FLOATS * sizeof(float)>>>(
        Ca, chains_w, gamma, beta, out);
}

// round 17
// speedup vs baseline: 1.1487x; 1.1156x over previous
#include <cuda_runtime.h>
#include <math.h>

#define B_DIM 8
#define L_DIM 2048
#define TOPK 30
#define NROWS (B_DIM * L_DIM)          // 16384
#define NEDGES (NROWS * TOPK)          // 491520
#define E_ELEMS ((size_t)NEDGES * 128) // 62914560
#define NFEAT 147

#define KP 84                           // padded fpair stride (conflict-free: 84 % 32 = 20)
#define NKS 10                          // k-steps of 16 (K padded to 160)
#define TSTRIDE 130                     // T smem row stride (even for LDS.64)
#define AW (16 * KP)                    // 1344 u32 per (warp, hi|lo)

// smem u32 offsets
#define OFF_BH 0
#define OFF_BL 10752
#define OFF_T  21504                    // floats, 66*130 = 8580
#define OFF_GM 30084
#define OFF_BT 30212
#define OFF_A  30340                    // 8 warps * 2688
#define SMEM_U32 (OFF_A + 8 * 2 * AW)   // 51844 u32 = 207376 B

// ---------------- device scratch ----------------
__device__ int   g_Eidx[NEDGES];
__device__ float g_Dnb[NEDGES];
__device__ float g_SH[NROWS * 3];
__device__ float g_T[66 * 128];
__device__ unsigned g_Wbh[128 * KP];    // bf16x2 weight pairs (hi)
__device__ unsigned g_Wbl[128 * KP];    // bf16x2 weight pairs (lo residual)
__device__ int   g_chainStride;
__device__ float g_Cx[NROWS], g_Cy[NROWS], g_Cz[NROWS];

static __device__ __forceinline__ unsigned long long u64min(unsigned long long a, unsigned long long b) {
    return a < b ? a : b;
}
static __device__ __forceinline__ float xla_dist(float dx, float dy, float dz) {
    float d2 = __fadd_rn(__fadd_rn(__fmul_rn(dx, dx), __fmul_rn(dy, dy)), __fmul_rn(dz, dz));
    return __fsqrt_rn(__fadd_rn(d2, 1e-6f));
}
#define CASW(x, y) { unsigned long long _mn = u64min(x, y); y = x ^ y ^ _mn; x = _mn; }

static __device__ __forceinline__ unsigned pack_lo(float r0, float r1) {
    unsigned d;
    asm("cvt.rn.bf16x2.f32 %0, %1, %2;" : "=r"(d) : "f"(r1), "f"(r0));  // r1->hi, r0->lo
    return d;
}
static __device__ __forceinline__ void mma_bf16(float* d,
        unsigned a0, unsigned a1, unsigned a2, unsigned a3,
        unsigned b0, unsigned b1) {
    asm volatile("mma.sync.aligned.m16n8k16.row.col.f32.bf16.bf16.f32 "
        "{%0,%1,%2,%3}, {%4,%5,%6,%7}, {%8,%9}, {%0,%1,%2,%3};"
        : "+f"(d[0]), "+f"(d[1]), "+f"(d[2]), "+f"(d[3])
        : "r"(a0), "r"(a1), "r"(a2), "r"(a3), "r"(b0), "r"(b1));
}

// ---------------- prep ----------------
__global__ void prep_kernel(const float* __restrict__ W_edge,
                            const float* __restrict__ W_pos,
                            const float* __restrict__ b_pos,
                            const unsigned int* __restrict__ chains_w,
                            const float* __restrict__ Ca) {
    int tid = blockIdx.x * blockDim.x + threadIdx.x;
    if (tid == 0) {
        int stride = 2;
        for (int t = 1; t < 512; t += 2)
            if (chains_w[t] != 0u) { stride = 1; break; }
        g_chainStride = stride;
    }
    if (tid < NROWS) {
        float x = Ca[tid * 3], y = Ca[tid * 3 + 1], z = Ca[tid * 3 + 2];
        g_Cx[tid] = x; g_Cy[tid] = y; g_Cz[tid] = z;
        float r = sqrtf(x * x + y * y + z * z);
        float phi = atan2f(y, x);
        float cp = cosf(phi);
        float s2 = 1.f - cp * cp, cp2 = cp * cp;
        const float INV4PI = 0.07957747154594767f;
        float f0 = sqrtf(INV4PI * INV4PI);
        float a10 = 3.f * INV4PI, a11 = 0.5f * a10, a1m = 2.f * a10;
        float f1 = sqrtf(a10 * a10 * cp2 + (a11 * a11 + 0.25f * a1m * a1m) * cp2 * s2);
        float a20 = 5.f * INV4PI, a21 = a20 / 6.f, a2m1 = a20 * 6.f;
        float a22 = a20 / 24.f, a2m2 = a20 * 24.f;
        float p20 = 0.5f * (3.f * cp2 - 1.f);
        float c2 = cosf(2.f * phi);
        float f2 = sqrtf(a20 * a20 * p20 * p20
                   + (9.f * a21 * a21 + 0.25f * a2m1 * a2m1) * cp2 * cp2 * s2
                   + (9.f * a22 * a22 + a2m2 * a2m2 * (1.f / 64.f)) * c2 * c2 * s2 * s2);
        float q = z / r;
        bool bad = !(q >= -1.f && q <= 1.f);
        if (bad || !(f0 == f0)) f0 = 0.f;
        if (bad || !(f1 == f1)) f1 = 0.f;
        if (bad || !(f2 == f2)) f2 = 0.f;
        g_SH[tid * 3] = f0; g_SH[tid * 3 + 1] = f1; g_SH[tid * 3 + 2] = f2;
    }
    if (tid < 66 * 128) {
        int d = tid >> 7, c = tid & 127;
        float s = 0.f;
        #pragma unroll
        for (int p = 0; p < 16; p++)
            s += W_edge[c * 163 + p] * (W_pos[p * 66 + d] + b_pos[p]);
        g_T[tid] = s;
    }
    if (tid < 128 * KP) {
        int ch = tid / KP, p = tid % KP;
        float w0 = 0.f, w1 = 0.f;
        int f0 = 2 * p, f1 = 2 * p + 1;
        if (f0 < NFEAT) {
            int col = (f0 < 144) ? (16 + f0) : (160 + (f0 - 144));
            w0 = W_edge[ch * 163 + col];
        }
        if (f1 < NFEAT) {
            int col = (f1 < 144) ? (16 + f1) : (160 + (f1 - 144));
            w1 = W_edge[ch * 163 + col];
        }
        unsigned b0 = __float_as_uint(w0), b1 = __float_as_uint(w1);
        g_Wbh[tid] = __byte_perm(b0, b1, 0x7632);
        float r0 = w0 - __uint_as_float(b0 & 0xFFFF0000u);
        float r1 = w1 - __uint_as_float(b1 & 0xFFFF0000u);
        g_Wbl[tid] = pack_lo(r0, r1);
    }
}

// ---------------- top-k (R13) ----------------
__global__ void __launch_bounds__(256) topk_kernel(const float* __restrict__ mask,
                                                   float* __restrict__ outIdx,
                                                   int writeIdx) {
    const int row = blockIdx.x;
    const int b = row >> 11, i = row & (L_DIM - 1);
    const int tid = threadIdx.x;
    const int warp = tid >> 5, lane = tid & 31;
    const int base = b << 11;
    float cx = g_Cx[base + i], cy = g_Cy[base + i], cz = g_Cz[base + i];
    float mi = mask[row];

    float Dv[8], mm[8];
    float lmax = 0.f;
    #pragma unroll
    for (int t = 0; t < 8; t++) {
        int j = tid + (t << 8);
        float dx = __fadd_rn(cx, -g_Cx[base + j]);
        float dy = __fadd_rn(cy, -g_Cy[base + j]);
        float dz = __fadd_rn(cz, -g_Cz[base + j]);
        float sd = xla_dist(dx, dy, dz);
        float mij = __fmul_rn(mi, mask[base + j]);
        float D = __fmul_rn(mij, sd);
        Dv[t] = D; mm[t] = mij;
        lmax = fmaxf(lmax, D);
    }
    __shared__ float sred[8];
    #pragma unroll
    for (int o = 16; o; o >>= 1) lmax = fmaxf(lmax, __shfl_xor_sync(0xffffffffu, lmax, o));
    if (lane == 0) sred[warp] = lmax;
    __syncthreads();
    float Dmax = sred[0];
    #pragma unroll
    for (int w = 1; w < 8; w++) Dmax = fmaxf(Dmax, sred[w]);

    unsigned long long k0, k1, k2, k3, k4, k5, k6, k7;
    {
        unsigned long long kk[8];
        #pragma unroll
        for (int t = 0; t < 8; t++) {
            float kf = __fadd_rn(Dv[t], __fmul_rn(__fadd_rn(1.f, -mm[t]), Dmax));
            kk[t] = ((unsigned long long)__float_as_uint(kf) << 32) | (unsigned)(tid + (t << 8));
        }
        k0 = kk[0]; k1 = kk[1]; k2 = kk[2]; k3 = kk[3];
        k4 = kk[4]; k5 = kk[5]; k6 = kk[6]; k7 = kk[7];
    }
    CASW(k0, k1); CASW(k2, k3); CASW(k4, k5); CASW(k6, k7);
    CASW(k0, k2); CASW(k1, k3); CASW(k4, k6); CASW(k5, k7);
    CASW(k1, k2); CASW(k5, k6);
    CASW(k0, k4); CASW(k1, k5); CASW(k2, k6); CASW(k3, k7);
    CASW(k2, k4); CASW(k3, k5);
    CASW(k1, k2); CASW(k3, k4); CASW(k5, k6);

    __shared__ unsigned long long sortedK[8][32][8];
    __shared__ unsigned long long warpTop[8][32];
    unsigned long long* myS = sortedK[warp][lane];
    myS[0] = k0; myS[1] = k1; myS[2] = k2; myS[3] = k3;
    myS[4] = k4; myS[5] = k5; myS[6] = k6; myS[7] = k7;

    const unsigned long long INF64 = 0xFFFFFFFFFFFFFFFFull;
    unsigned long long h = k0;
    int pos = 0;
    for (int r = 0; r < TOPK; r++) {
        unsigned v = (unsigned)(h >> 32);
        unsigned m = v;
        #pragma unroll
        for (int o = 16; o; o >>= 1) m = min(m, __shfl_xor_sync(0xffffffffu, m, o));
        unsigned eq = __ballot_sync(0xffffffffu, v == m);
        int wl;
        if ((eq & (eq - 1)) == 0u) {
            wl = __ffs(eq) - 1;
        } else {
            unsigned ic = (v == m) ? (unsigned)h : 0xFFFFFFFFu;
            unsigned mi2 = ic;
            #pragma unroll
            for (int o = 16; o; o >>= 1) mi2 = min(mi2, __shfl_xor_sync(0xffffffffu, mi2, o));
            wl = __ffs(__ballot_sync(0xffffffffu, ic == mi2)) - 1;
        }
        unsigned long long hw = __shfl_sync(0xffffffffu, h, wl);
        if (lane == 0) warpTop[warp][r] = hw;
        if (lane == wl) {
            pos++;
            h = (pos < 8) ? myS[pos] : INF64;
        }
    }
    if (lane == 0) { warpTop[warp][30] = INF64; warpTop[warp][31] = INF64; }
    __syncthreads();

    if (tid < 8 * TOPK) {
        int lw = tid / TOPK, lp = tid - lw * TOPK;
        unsigned long long c = warpTop[lw][lp];
        int rank = lp;
        #pragma unroll
        for (int w = 0; w < 8; w++) {
            if (w == lw) continue;
            const unsigned long long* L = warpTop[w];
            int p = 0;
            if (L[p + 15] < c) p += 16;
            if (L[p + 7]  < c) p += 8;
            if (L[p + 3]  < c) p += 4;
            if (L[p + 1]  < c) p += 2;
            if (L[p]      < c) p += 1;
            rank += p;
        }
        if (rank < TOPK) {
            int j = (int)(c & 0xFFFFFFFFull);
            g_Eidx[row * TOPK + rank] = j;
            g_Dnb[row * TOPK + rank] = __uint_as_float((unsigned)(c >> 32));
            if (writeIdx) outIdx[row * TOPK + rank] = (float)j;
        }
    }
}

// ---------------- edge kernel: tensor-core bf16 split-precision GEMM ----------------
__global__ void __launch_bounds__(256, 1)
edge_kernel(const float* __restrict__ Ca,
            const unsigned int* __restrict__ chains_w,
            const float* __restrict__ gamma,
            const float* __restrict__ beta,
            float* __restrict__ outE) {
    extern __shared__ unsigned smU[];
    float* smF = (float*)smU;
    const int tid = threadIdx.x;
    const int warp = tid >> 5, lane = tid & 31;
    const int g = lane >> 2, tq = lane & 3;

    // cooperative loads
    for (int i = tid; i < 128 * KP; i += 256) { smU[OFF_BH + i] = g_Wbh[i]; smU[OFF_BL + i] = g_Wbl[i]; }
    for (int i = tid; i < 66 * 128; i += 256) smF[OFF_T + (i >> 7) * TSTRIDE + (i & 127)] = g_T[i];
    if (tid < 128) { smF[OFF_GM + tid] = gamma[tid]; smF[OFF_BT + tid] = beta[tid]; }
    __syncthreads();

    unsigned* Ah = smU + OFF_A + warp * (2 * AW);
    unsigned* Al = Ah + AW;

    const int row = blockIdx.x * 8 + warp;
    const int b = row >> 11, i = row & (L_DIM - 1);
    const float* Cb = Ca + (size_t)(b << 11) * 3;
    const int cstr = g_chainStride;

    float3 Ci  = make_float3(Cb[i * 3], Cb[i * 3 + 1], Cb[i * 3 + 2]);
    float3 Ci0 = (i > 0) ? make_float3(Cb[(i - 1) * 3], Cb[(i - 1) * 3 + 1], Cb[(i - 1) * 3 + 2])
                         : make_float3(0.f, 0.f, 0.f);
    float3 Ci2 = (i < L_DIM - 1) ? make_float3(Cb[(i + 1) * 3], Cb[(i + 1) * 3 + 1], Cb[(i + 1) * 3 + 2])
                                 : make_float3(0.f, 0.f, 0.f);
    unsigned chi = chains_w[(size_t)row * cstr];

    int li = (lane >= 1) ? ((lane - 1) & 7) : 0;
    int ac = (int)((0x22110020u >> (li << 2)) & 3u);
    int bc = (int)((0x10202120u >> (li << 2)) & 3u);
    float3 Apt = (ac == 0) ? Ci0 : ((ac == 1) ? Ci : Ci2);

    for (int tile = 0; tile < 2; tile++) {
        const int base = tile ? 14 : 0;

        int jj = 0; float D0 = 0.f; int didx = 65;
        if (lane < 16) {
            jj = g_Eidx[row * TOPK + base + lane];
            D0 = g_Dnb[row * TOPK + base + lane];
            unsigned cj = chains_w[(size_t)((b << 11) + jj) * cstr];
            int off = i - jj + 32;
            off = off < 0 ? 0 : (off > 64 ? 64 : off);
            didx = (chi == cj) ? off : 65;
        }
        __syncwarp();

        // ---- feature gen: bf16 hi/lo pairs into A ----
        for (int e = 0; e < 16; e++) {
            int   je  = __shfl_sync(0xffffffffu, jj, e);
            float D0e = __shfl_sync(0xffffffffu, D0, e);
            float dv = D0e;
            int jb = je + bc - 1;
            bool valid = (bc == 1) || (jb >= 0 && jb <= L_DIM - 1);
            float bx = 0.f, by = 0.f, bz = 0.f;
            if (lane >= 1 && lane <= 8 && valid) {
                bx = Cb[jb * 3]; by = Cb[jb * 3 + 1]; bz = Cb[jb * 3 + 2];
            }
            if (lane >= 1 && lane <= 8) {
                float dx = Apt.x - bx, dy = Apt.y - by, dz = Apt.z - bz;
                dv = sqrtf(dx * dx + dy * dy + dz * dz + 1e-6f);
            }
            #pragma unroll
            for (int t = 0; t < 3; t++) {
                int p = lane + (t << 5);
                int srcl = p >> 3; if (srcl > 8) srcl = 0;
                float dd = __shfl_sync(0xffffffffu, dv, srcl);
                if (p < 80) {
                    float v0, v1;
                    if (p < 72) {
                        float m0 = (float)((2 * p) & 15);
                        float u0 = (dd - (2.f + m0 * (4.f / 3.f))) * 0.8f;
                        float u1 = (dd - (2.f + (m0 + 1.f) * (4.f / 3.f))) * 0.8f;
                        v0 = __expf(-u0 * u0);
                        v1 = __expf(-u1 * u1);
                    } else if (p == 72) {
                        v0 = g_SH[((b << 11) + je) * 3];
                        v1 = g_SH[((b << 11) + je) * 3 + 1];
                    } else if (p == 73) {
                        v0 = g_SH[((b << 11) + je) * 3 + 2];
                        v1 = 0.f;
                    } else { v0 = 0.f; v1 = 0.f; }
                    unsigned b0 = __float_as_uint(v0), b1 = __float_as_uint(v1);
                    Ah[e * KP + p] = __byte_perm(b0, b1, 0x7632);
                    float r0 = v0 - __uint_as_float(b0 & 0xFFFF0000u);
                    float r1 = v1 - __uint_as_float(b1 & 0xFFFF0000u);
                    Al[e * KP + p] = pack_lo(r0, r1);
                }
            }
        }
        __syncwarp();

        // ---- MMA: 3 split passes, D[16 edges][128 ch] ----
        float d[16][4];
        #pragma unroll
        for (int nt = 0; nt < 16; nt++) { d[nt][0] = 0.f; d[nt][1] = 0.f; d[nt][2] = 0.f; d[nt][3] = 0.f; }

        #pragma unroll 1
        for (int k = 0; k < NKS; k++) {
            int col = 8 * k + tq;
            unsigned ah0 = Ah[g * KP + col], ah1 = Ah[(g + 8) * KP + col];
            unsigned ah2 = Ah[g * KP + col + 4], ah3 = Ah[(g + 8) * KP + col + 4];
            unsigned al0 = Al[g * KP + col], al1 = Al[(g + 8) * KP + col];
            unsigned al2 = Al[g * KP + col + 4], al3 = Al[(g + 8) * KP + col + 4];
            #pragma unroll
            for (int nt = 0; nt < 16; nt++) {
                int wi = (nt * 8 + g) * KP + col;
                unsigned bh0 = smU[OFF_BH + wi], bh1 = smU[OFF_BH + wi + 4];
                mma_bf16(d[nt], ah0, ah1, ah2, ah3, bh0, bh1);
            }
            #pragma unroll
            for (int nt = 0; nt < 16; nt++) {
                int wi = (nt * 8 + g) * KP + col;
                unsigned bl0 = smU[OFF_BL + wi], bl1 = smU[OFF_BL + wi + 4];
                mma_bf16(d[nt], ah0, ah1, ah2, ah3, bl0, bl1);
            }
            #pragma unroll
            for (int nt = 0; nt < 16; nt++) {
                int wi = (nt * 8 + g) * KP + col;
                unsigned bh0 = smU[OFF_BH + wi], bh1 = smU[OFF_BH + wi + 4];
                mma_bf16(d[nt], al0, al1, al2, al3, bh0, bh1);
            }
        }

        // ---- epilogue: +T, LayerNorm (quad reductions), store ----
        int de0 = __shfl_sync(0xffffffffu, didx, g);
        int de1 = __shfl_sync(0xffffffffu, didx, g + 8);
        #pragma unroll
        for (int nt = 0; nt < 16; nt++) {
            float2 t0 = *(const float2*)&smF[OFF_T + de0 * TSTRIDE + nt * 8 + 2 * tq];
            float2 t1 = *(const float2*)&smF[OFF_T + de1 * TSTRIDE + nt * 8 + 2 * tq];
            d[nt][0] += t0.x; d[nt][1] += t0.y;
            d[nt][2] += t1.x; d[nt][3] += t1.y;
        }
        float s0 = 0.f, q0 = 0.f, s1 = 0.f, q1 = 0.f;
        #pragma unroll
        for (int nt = 0; nt < 16; nt++) {
            s0 += d[nt][0] + d[nt][1];
            q0 += d[nt][0] * d[nt][0] + d[nt][1] * d[nt][1];
            s1 += d[nt][2] + d[nt][3];
            q1 += d[nt][2] * d[nt][2] + d[nt][3] * d[nt][3];
        }
        #pragma unroll
        for (int o = 1; o <= 2; o <<= 1) {
            s0 += __shfl_xor_sync(0xffffffffu, s0, o);
            q0 += __shfl_xor_sync(0xffffffffu, q0, o);
            s1 += __shfl_xor_sync(0xffffffffu, s1, o);
            q1 += __shfl_xor_sync(0xffffffffu, q1, o);
        }
        float mu0 = s0 * (1.f / 128.f);
        float mu1 = s1 * (1.f / 128.f);
        float rstd0 = rsqrtf(fmaxf(q0 * (1.f / 128.f) - mu0 * mu0, 0.f) + 1e-5f);
        float rstd1 = rsqrtf(fmaxf(q1 * (1.f / 128.f) - mu1 * mu1, 0.f) + 1e-5f);

        size_t eg0 = (size_t)(row * TOPK + base + g) * 128;
        size_t eg1 = (size_t)(row * TOPK + base + g + 8) * 128;
        #pragma unroll
        for (int nt = 0; nt < 16; nt++) {
            int ch = nt * 8 + 2 * tq;
            float2 gm = *(const float2*)&smF[OFF_GM + ch];
            float2 bt = *(const float2*)&smF[OFF_BT + ch];
            float2 o0, o1;
            o0.x = (d[nt][0] - mu0) * rstd0 * gm.x + bt.x;
            o0.y = (d[nt][1] - mu0) * rstd0 * gm.y + bt.y;
            o1.x = (d[nt][2] - mu1) * rstd1 * gm.x + bt.x;
            o1.y = (d[nt][3] - mu1) * rstd1 * gm.y + bt.y;
            *(float2*)&outE[eg0 + ch] = o0;
            *(float2*)&outE[eg1 + ch] = o1;
        }
        __syncwarp();
    }
}

// ---------------- launch ----------------
extern "C" void kernel_launch(void* const* d_in, const int* in_sizes, int n_in,
                              void* d_out, int out_size) {
    const float* Ca     = (const float*)d_in[0];
    const float* mask   = (const float*)d_in[1];
    const unsigned int* chains_w = (const unsigned int*)d_in[3];
    const float* W_pos  = (const float*)d_in[4];
    const float* b_pos  = (const float*)d_in[5];
    const float* W_edge = (const float*)d_in[6];
    const float* gamma  = (const float*)d_in[7];
    const float* beta   = (const float*)d_in[8];
    float* out = (float*)d_out;

    int writeIdx = ((size_t)out_size >= E_ELEMS + (size_t)NEDGES) ? 1 : 0;

    prep_kernel<<<(NROWS + 255) / 256, 256>>>(W_edge, W_pos, b_pos, chains_w, Ca);
    topk_kernel<<<NROWS, 256>>>(mask, out + E_ELEMS, writeIdx);

    cudaFuncSetAttribute(edge_kernel, cudaFuncAttributeMaxDynamicSharedMemorySize,
                         SMEM_U32 * 4);
    edge_kernel<<<NROWS / 8, 256, SMEM_U32 * 4>>>(Ca, chains_w, gamma, beta, out);
}